// round 14
// baseline (speedup 1.0000x reference)
#include <cuda_runtime.h>
#include <cuda_bf16.h>
#include <math.h>
#include <stdint.h>

#define B_  512
#define T_  512
#define L_  64
#define H_  512
#define G3_ 1536
#define XW_ 575

#define SLOT_  92160
#define SMTOT_ 184320

// ------------------------- device scratch (no allocs) -----------------------
__device__ __align__(16) float g_H1fin[(size_t)B_ * H_];
__device__ __align__(16) float g_H2[(size_t)L_ * B_ * H_];
__device__ __align__(16) __nv_bfloat16 g_X2[(size_t)L_ * B_ * 1024]; // [t][b][hi|lo]
__device__ __align__(16) __nv_bfloat16 g_W0h[(size_t)G3_ * H_], g_W0l[(size_t)G3_ * H_];
__device__ __align__(16) __nv_bfloat16 g_W1h[(size_t)G3_ * H_], g_W1l[(size_t)G3_ * H_];
__device__ __align__(16) __nv_bfloat16 g_W2h[(size_t)G3_ * H_], g_W2l[(size_t)G3_ * H_];
__device__ __align__(16) __nv_bfloat16 g_W3h[(size_t)G3_ * H_], g_W3l[(size_t)G3_ * H_];
__device__ __align__(16) __nv_bfloat16 g_H1h[2][(size_t)B_ * H_], g_H1l[2][(size_t)B_ * H_];
__device__ __align__(16) __nv_bfloat16 g_H2h[2][(size_t)B_ * H_], g_H2l[2][(size_t)B_ * H_];
__device__ unsigned g_bars[512];

__device__ __forceinline__ float sigm(float v) { return 1.f / (1.f + __expf(-v)); }

__device__ __forceinline__ uint32_t smem_u32(const void* p) {
    uint32_t a;
    asm("{ .reg .u64 t; cvta.to.shared.u64 t, %1; cvt.u32.u64 %0, t; }" : "=r"(a) : "l"(p));
    return a;
}
__device__ __forceinline__ void ldsm4(uint32_t* r, uint32_t addr) {
    asm volatile("ldmatrix.sync.aligned.m8n8.x4.shared.b16 {%0,%1,%2,%3}, [%4];"
                 : "=r"(r[0]), "=r"(r[1]), "=r"(r[2]), "=r"(r[3]) : "r"(addr));
}
__device__ __forceinline__ void mma16816(float* c, const uint32_t* a, uint32_t b0, uint32_t b1) {
    asm volatile("mma.sync.aligned.m16n8k16.row.col.f32.bf16.bf16.f32 "
                 "{%0,%1,%2,%3}, {%4,%5,%6,%7}, {%8,%9}, {%0,%1,%2,%3};"
                 : "+f"(c[0]), "+f"(c[1]), "+f"(c[2]), "+f"(c[3])
                 : "r"(a[0]), "r"(a[1]), "r"(a[2]), "r"(a[3]), "r"(b0), "r"(b1));
}
__device__ __forceinline__ void split2(float a, __nv_bfloat16& h, __nv_bfloat16& l) {
    h = __float2bfloat16_rn(a);
    l = __float2bfloat16_rn(a - __bfloat162float(h));
}
__device__ __forceinline__ void cp16(uint32_t dst, const void* src) {
    asm volatile("cp.async.cg.shared.global [%0], [%1], 16;" :: "r"(dst), "l"(src));
}
__device__ __forceinline__ void cp_commit() {
    asm volatile("cp.async.commit_group;" ::: "memory");
}
template <int N> __device__ __forceinline__ void cp_wait() {
    asm volatile("cp.async.wait_group %0;" :: "n"(N) : "memory");
}
__device__ __forceinline__ void stage_cp(uint32_t dst, const __nv_bfloat16* src,
                                         int rows, int stride, int tid, int nthr) {
    for (int i = tid; i < rows * 4; i += nthr) {
        int r = i >> 2, q = i & 3;
        cp16(dst + r * 80 + q * 16, src + (size_t)r * stride + q * 8);
    }
}

// ---------------------------------------------------------------------------
// Prep kernels
// ---------------------------------------------------------------------------
__global__ __launch_bounds__(256) void k_prep_w(const float* __restrict__ W0,
                                                const float* __restrict__ W1,
                                                const float* __restrict__ W2,
                                                const float* __restrict__ W3) {
    size_t i = (size_t)blockIdx.x * 256 + threadIdx.x;
    if (i >= (size_t)G3_ * H_) return;
    __nv_bfloat16 h, l;
    split2(W0[i], h, l); g_W0h[i] = h; g_W0l[i] = l;
    split2(W1[i], h, l); g_W1h[i] = h; g_W1l[i] = l;
    split2(W2[i], h, l); g_W2h[i] = h; g_W2l[i] = l;
    split2(W3[i], h, l); g_W3h[i] = h; g_W3l[i] = l;
}

__global__ __launch_bounds__(256) void k_prep_h(const float* __restrict__ h1i,
                                                const float* __restrict__ h2i) {
    size_t i = (size_t)blockIdx.x * 256 + threadIdx.x;
    if (i >= (size_t)B_ * H_) return;
    __nv_bfloat16 h, l;
    split2(h1i[i], h, l); g_H1h[1][i] = h; g_H1l[1][i] = l;
    split2(h2i[i], h, l); g_H2h[1][i] = h; g_H2l[1][i] = l;
}

__global__ __launch_bounds__(256) void k_prep_x(const float* __restrict__ x) {
    size_t i = (size_t)blockIdx.x * 256 + threadIdx.x;
    if (i >= (size_t)L_ * B_ * H_) return;
    int k = (int)(i % H_);
    int b = (int)((i / H_) % B_);
    int t = (int)(i / ((size_t)B_ * H_));
    __nv_bfloat16 h, l;
    split2(x[(size_t)b * XW_ + t + k], h, l);
    size_t o = ((size_t)t * B_ + b) * 1024;
    g_X2[o + k] = h; g_X2[o + 512 + k] = l;
}

// ---------------------------------------------------------------------------
// k_steps: persistent recurrence, 4-way matmul warp specialization.
// Barrier-decoupled staging:
//   - W (step-invariant) chunks 0,1 and X (static) chunks 0,1 of the NEXT
//     iteration are prestaged during the epilogue phase.
//   - Only h-panels of chunks 0,1 (2x20KB) are staged after the barrier.
//   - Exchange buffers in slot0's W region (dead post-K-loop); W(0) prestage
//     reuses that region after the epilogue consumes EX.
// Slot layout: A1h@0 A1l@5120 A2h@10240 A2l@15360 AXh@20480 AXl@25600
//              W@30720 + grp*15360 (hi 3x2560, lo +7680)
// EX1 (G1->G2) @ slot0+30720, EX2 (G3->G0) @ slot0+55296.
// ---------------------------------------------------------------------------
__global__ __launch_bounds__(512, 1) void k_steps(const float* __restrict__ h1i,
                                                  const float* __restrict__ h2i,
                                                  const float* __restrict__ bih1,
                                                  const float* __restrict__ bhh1,
                                                  const float* __restrict__ bih2,
                                                  const float* __restrict__ bhh2) {
    extern __shared__ char sm[];
    const uint32_t smb = smem_u32(sm);
    const int tid = threadIdx.x;
    const int bid = blockIdx.x;
    const int j0 = (bid & 15) * 32;
    const int m0 = (bid >> 4) * 64;
    const int grp = bid >> 4;
    const int wid = tid >> 5, lane = tid & 31;
    const int group = wid >> 2;            // 0:W1, 1:W2, 2:W3, 3:W0(gi)
    const int wg = wid & 3;
    const int wm = (wg & 1) * 32;
    const int wn16 = (wg >> 1) * 16;
    const int arow = lane & 15, acol = (lane >> 4) * 8;
    const int brow = (lane & 7) + ((lane >> 4) << 3), bcol = ((lane >> 3) & 1) * 8;
    const int row = lane >> 2, colp = (lane & 3) * 2;

    // biases per group
    float2 bs0[2], bs1[2], bs2[2], bs3[2];
    float2 hp[2][2][2];   // G0 -> h1 carry, G2 -> h2 carry
#pragma unroll
    for (int nf = 0; nf < 2; nf++) {
        int jg = j0 + wn16 + nf * 8 + colp;
        float2 u, v;
        if (group == 0) {
            u = *(const float2*)(bih1 + jg);        v = *(const float2*)(bhh1 + jg);
            bs0[nf] = make_float2(u.x + v.x, u.y + v.y);
            u = *(const float2*)(bih1 + 512 + jg);  v = *(const float2*)(bhh1 + 512 + jg);
            bs1[nf] = make_float2(u.x + v.x, u.y + v.y);
            bs2[nf] = *(const float2*)(bih1 + 1024 + jg);
            bs3[nf] = *(const float2*)(bhh1 + 1024 + jg);
        } else if (group == 2) {
            u = *(const float2*)(bih2 + jg);        v = *(const float2*)(bhh2 + jg);
            bs0[nf] = make_float2(u.x + v.x, u.y + v.y);
            u = *(const float2*)(bih2 + 512 + jg);  v = *(const float2*)(bhh2 + 512 + jg);
            bs1[nf] = make_float2(u.x + v.x, u.y + v.y);
            bs2[nf] = *(const float2*)(bih2 + 1024 + jg);
            bs3[nf] = *(const float2*)(bhh2 + 1024 + jg);
        } else {
            bs0[nf] = bs1[nf] = bs2[nf] = bs3[nf] = make_float2(0.f, 0.f);
        }
#pragma unroll
        for (int mf = 0; mf < 2; mf++)
#pragma unroll
            for (int hh = 0; hh < 2; hh++) {
                int m = m0 + wm + mf * 16 + row + hh * 8;
                const float* src = (group == 2) ? h2i : h1i;
                hp[mf][nf][hh] = *(const float2*)(src + (size_t)m * H_ + jg);
            }
    }

    auto stageW = [&](int c) {
        const int k0 = c * 32;
        uint32_t d = smb + (uint32_t)(c & 1) * SLOT_ + 30720u;
#pragma unroll
        for (int g = 0; g < 3; g++) {
            const size_t wo = (size_t)(g * 512 + j0) * H_ + k0;
            stage_cp(d +     0 + g * 2560, g_W1h + wo, 32, H_, tid, 512);
            stage_cp(d +  7680 + g * 2560, g_W1l + wo, 32, H_, tid, 512);
            stage_cp(d + 15360 + g * 2560, g_W2h + wo, 32, H_, tid, 512);
            stage_cp(d + 23040 + g * 2560, g_W2l + wo, 32, H_, tid, 512);
            stage_cp(d + 30720 + g * 2560, g_W3h + wo, 32, H_, tid, 512);
            stage_cp(d + 38400 + g * 2560, g_W3l + wo, 32, H_, tid, 512);
            stage_cp(d + 46080 + g * 2560, g_W0h + wo, 32, H_, tid, 512);
            stage_cp(d + 53760 + g * 2560, g_W0l + wo, 32, H_, tid, 512);
        }
    };
    auto stage_h = [&](int c, int op1, int op2) {
        const int k0 = c * 32;
        uint32_t d = smb + (uint32_t)(c & 1) * SLOT_;
        stage_cp(d,         g_H1h[op1] + (size_t)m0 * H_ + k0, 64, H_, tid, 512);
        stage_cp(d + 5120,  g_H1l[op1] + (size_t)m0 * H_ + k0, 64, H_, tid, 512);
        stage_cp(d + 10240, g_H2h[op2] + (size_t)m0 * H_ + k0, 64, H_, tid, 512);
        stage_cp(d + 15360, g_H2l[op2] + (size_t)m0 * H_ + k0, 64, H_, tid, 512);
    };
    auto stage_x = [&](int c, int ti) {
        const int k0 = c * 32;
        uint32_t d = smb + (uint32_t)(c & 1) * SLOT_;
        const __nv_bfloat16* X = g_X2 + ((size_t)ti * B_ + m0) * 1024;
        stage_cp(d + 20480, X + k0,       64, 1024, tid, 512);
        stage_cp(d + 25600, X + 512 + k0, 64, 1024, tid, 512);
    };

    const uint32_t abase_off = (group == 2) ? 10240u : ((group == 3) ? 20480u : 0u);
    const uint32_t wbase_off = 30720u + (uint32_t)group * 15360u;
    const uint32_t ex1 = smb + 30720u;            // slot0 W region (G1 -> G2)
    const uint32_t ex2 = smb + 30720u + 24576u;   // slot0 W region (G3 -> G0)
    const int exi = ((wg * 32 + lane) * 48) * 4;

    // bootstrap: X(0), X(1), W(1) then W(0)
    stage_x(0, 0); stage_x(1, 0); stageW(1); cp_commit();
    stageW(0); cp_commit();

    unsigned barT = 0;
    for (int i = 0; i <= L_; i++) {
        const int op1 = (i + 1) & 1;
        const int op2 = i & 1;
        const int ti = (i < L_) ? i : 0;

        // barrier-dependent staging: only h-panels of chunks 0,1
        stage_h(0, op1, op2); cp_commit();
        stage_h(1, op1, op2); cp_commit();

        float acc[3][2][2][4];
#pragma unroll
        for (int g = 0; g < 3; g++)
#pragma unroll
            for (int mf = 0; mf < 2; mf++)
#pragma unroll
                for (int nf = 0; nf < 2; nf++)
#pragma unroll
                    for (int q = 0; q < 4; q++) acc[g][mf][nf][q] = 0.f;

        for (int gc = 0; gc < 16; gc++) {
            cp_wait<0>();
            __syncthreads();
            if (gc >= 1 && gc <= 14) {
                stageW(gc + 1); stage_h(gc + 1, op1, op2); stage_x(gc + 1, ti);
                cp_commit();
            }
            const uint32_t Ab = smb + (uint32_t)(gc & 1) * SLOT_;
            const uint32_t abase = Ab + abase_off;
            const uint32_t wbase = Ab + wbase_off;
#pragma unroll
            for (int h = 0; h < 2; h++) {
                const int c0 = h * 16;
                uint32_t aH[2][4], aL[2][4];
#pragma unroll
                for (int mf = 0; mf < 2; mf++) {
                    uint32_t ao = ((wm + mf * 16 + arow) * 40 + c0 + acol) * 2;
                    ldsm4(aH[mf], abase + ao);
                    ldsm4(aL[mf], abase + 5120 + ao);
                }
                const uint32_t bo = ((wn16 + brow) * 40 + c0 + bcol) * 2;
#pragma unroll
                for (int g = 0; g < 3; g++) {
                    uint32_t bh[4], bl[4];
                    ldsm4(bh, wbase + g * 2560 + bo);
                    ldsm4(bl, wbase + 7680 + g * 2560 + bo);
#pragma unroll
                    for (int mf = 0; mf < 2; mf++)
#pragma unroll
                        for (int nf = 0; nf < 2; nf++) {
                            float* a = acc[g][mf][nf];
                            mma16816(a, aH[mf], bh[nf * 2], bh[nf * 2 + 1]);
                            mma16816(a, aH[mf], bl[nf * 2], bl[nf * 2 + 1]);
                            mma16816(a, aL[mf], bh[nf * 2], bh[nf * 2 + 1]);
                        }
                }
            }
        }
        cp_wait<0>();
        __syncthreads();   // all ldsm done; slot regions now dead

        // exchanges into slot0 W region (dead until W(0) prestage below)
        if (group == 1) {
#pragma unroll
            for (int g = 0; g < 3; g++)
#pragma unroll
                for (int mf = 0; mf < 2; mf++)
#pragma unroll
                    for (int nf = 0; nf < 2; nf++)
#pragma unroll
                        for (int q = 0; q < 4; q++) {
                            uint32_t addr = ex1 + exi + (((g * 2 + mf) * 2 + nf) * 4 + q) * 4;
                            asm volatile("st.shared.f32 [%0], %1;" :: "r"(addr), "f"(acc[g][mf][nf][q]));
                        }
        }
        if (group == 3) {
#pragma unroll
            for (int g = 0; g < 3; g++)
#pragma unroll
                for (int mf = 0; mf < 2; mf++)
#pragma unroll
                    for (int nf = 0; nf < 2; nf++)
#pragma unroll
                        for (int q = 0; q < 4; q++) {
                            uint32_t addr = ex2 + exi + (((g * 2 + mf) * 2 + nf) * 4 + q) * 4;
                            asm volatile("st.shared.f32 [%0], %1;" :: "r"(addr), "f"(acc[g][mf][nf][q]));
                        }
        }
        __syncthreads();   // exchanges visible

        // barrier-independent prestage for NEXT iteration: X(0), X(1), W(1)
        if (i < L_) {
            int ti2 = (i + 1 < L_) ? (i + 1) : (L_ - 1);
            stage_x(0, ti2); stage_x(1, ti2); stageW(1);
            cp_commit();
        }

        // ---- G0: layer-1 epilogue -> h1(i), consuming G3's gi accumulators ----
        if (group == 0 && i < L_) {
            __nv_bfloat16* hhN = g_H1h[i & 1];
            __nv_bfloat16* hlN = g_H1l[i & 1];
#pragma unroll
            for (int mf = 0; mf < 2; mf++)
#pragma unroll
                for (int nf = 0; nf < 2; nf++) {
                    int jg = j0 + wn16 + nf * 8 + colp;
#pragma unroll
                    for (int hh = 0; hh < 2; hh++) {
                        int m = m0 + wm + mf * 16 + row + hh * 8;
                        float exv[6];
#pragma unroll
                        for (int g = 0; g < 3; g++)
#pragma unroll
                            for (int q = 0; q < 2; q++) {
                                uint32_t addr = ex2 + exi + (((g * 2 + mf) * 2 + nf) * 4 + hh * 2 + q) * 4;
                                asm volatile("ld.shared.f32 %0, [%1];" : "=f"(exv[g * 2 + q]) : "r"(addr));
                            }
                        float r0 = sigm(exv[0] + acc[0][mf][nf][hh * 2] + bs0[nf].x);
                        float r1 = sigm(exv[1] + acc[0][mf][nf][hh * 2 + 1] + bs0[nf].y);
                        float z0 = sigm(exv[2] + acc[1][mf][nf][hh * 2] + bs1[nf].x);
                        float z1 = sigm(exv[3] + acc[1][mf][nf][hh * 2 + 1] + bs1[nf].y);
                        float n0 = tanhf(exv[4] + bs2[nf].x + r0 * (acc[2][mf][nf][hh * 2] + bs3[nf].x));
                        float n1 = tanhf(exv[5] + bs2[nf].y + r1 * (acc[2][mf][nf][hh * 2 + 1] + bs3[nf].y));
                        float h0 = (1.f - z0) * n0 + z0 * hp[mf][nf][hh].x;
                        float h1 = (1.f - z1) * n1 + z1 * hp[mf][nf][hh].y;
                        hp[mf][nf][hh] = make_float2(h0, h1);
                        __nv_bfloat16 x0, y0, x1, y1;
                        split2(h0, x0, y0); split2(h1, x1, y1);
                        __nv_bfloat162 hv; hv.x = x0; hv.y = x1;
                        __nv_bfloat162 lv; lv.x = y0; lv.y = y1;
                        *(__nv_bfloat162*)(hhN + (size_t)m * H_ + jg) = hv;
                        *(__nv_bfloat162*)(hlN + (size_t)m * H_ + jg) = lv;
                        if (i == L_ - 1)
                            *(float2*)(g_H1fin + (size_t)m * H_ + jg) = make_float2(h0, h1);
                    }
                }
        }

        // ---- G2: layer-2 epilogue -> h2(i-1), consuming G1's gi2 accumulators ----
        if (group == 2 && i > 0) {
            const int t2 = i - 1;
            float* h2new = g_H2 + (size_t)t2 * B_ * H_;
            __nv_bfloat16* hhN = g_H2h[t2 & 1];
            __nv_bfloat16* hlN = g_H2l[t2 & 1];
#pragma unroll
            for (int mf = 0; mf < 2; mf++)
#pragma unroll
                for (int nf = 0; nf < 2; nf++) {
                    int jg = j0 + wn16 + nf * 8 + colp;
#pragma unroll
                    for (int hh = 0; hh < 2; hh++) {
                        int m = m0 + wm + mf * 16 + row + hh * 8;
                        float exv[6];
#pragma unroll
                        for (int g = 0; g < 3; g++)
#pragma unroll
                            for (int q = 0; q < 2; q++) {
                                uint32_t addr = ex1 + exi + (((g * 2 + mf) * 2 + nf) * 4 + hh * 2 + q) * 4;
                                asm volatile("ld.shared.f32 %0, [%1];" : "=f"(exv[g * 2 + q]) : "r"(addr));
                            }
                        float r0 = sigm(acc[0][mf][nf][hh * 2] + exv[0] + bs0[nf].x);
                        float r1 = sigm(acc[0][mf][nf][hh * 2 + 1] + exv[1] + bs0[nf].y);
                        float z0 = sigm(acc[1][mf][nf][hh * 2] + exv[2] + bs1[nf].x);
                        float z1 = sigm(acc[1][mf][nf][hh * 2 + 1] + exv[3] + bs1[nf].y);
                        float n0 = tanhf(exv[4] + bs2[nf].x + r0 * (acc[2][mf][nf][hh * 2] + bs3[nf].x));
                        float n1 = tanhf(exv[5] + bs2[nf].y + r1 * (acc[2][mf][nf][hh * 2 + 1] + bs3[nf].y));
                        float h0 = (1.f - z0) * n0 + z0 * hp[mf][nf][hh].x;
                        float h1 = (1.f - z1) * n1 + z1 * hp[mf][nf][hh].y;
                        hp[mf][nf][hh] = make_float2(h0, h1);
                        *(float2*)(h2new + (size_t)m * H_ + jg) = make_float2(h0, h1);
                        __nv_bfloat16 x0, y0, x1, y1;
                        split2(h0, x0, y0); split2(h1, x1, y1);
                        __nv_bfloat162 hv; hv.x = x0; hv.y = x1;
                        __nv_bfloat162 lv; lv.x = y0; lv.y = y1;
                        *(__nv_bfloat162*)(hhN + (size_t)m * H_ + jg) = hv;
                        *(__nv_bfloat162*)(hlN + (size_t)m * H_ + jg) = lv;
                    }
                }
        }

        __syncthreads();   // EX consumed -> slot0 W region reusable

        // W(0) prestage (overwrites EX region)
        if (i < L_) { stageW(0); cp_commit(); }

        // ---- per-m-group barrier ----
        __threadfence();
        __syncthreads();
        if (tid == 0) atomicAdd(&g_bars[grp * 32], 1u);
        barT += 16;
        if (tid == 0) {
            while (*(volatile unsigned*)&g_bars[grp * 32] < barT) { }
        }
        __syncthreads();
    }
}

// ---------------------------------------------------------------------------
__global__ __launch_bounds__(256) void k_fc(const float* __restrict__ Wfc,
                                            const float* __restrict__ bfc,
                                            float* __restrict__ out) {
    int w = (blockIdx.x * 256 + threadIdx.x) >> 5;
    int lane = threadIdx.x & 31;
    int b = w >> 6, tt = w & 63;
    const float* h = g_H2 + ((size_t)tt * B_ + b) * H_;
    float s = 0.f;
#pragma unroll
    for (int q = 0; q < H_ / 32; q++) s += h[lane + 32 * q] * Wfc[lane + 32 * q];
#pragma unroll
    for (int off = 16; off; off >>= 1) s += __shfl_down_sync(0xffffffffu, s, off);
    if (lane == 0) out[(size_t)b * L_ + tt] = s + bfc[0];
}

__global__ __launch_bounds__(256) void k_copy(float* __restrict__ out) {
    int i = blockIdx.x * 256 + threadIdx.x;
    const int n = B_ * H_;
    if (i < n) {
        out[B_ * L_ + i] = g_H1fin[i];
        out[B_ * L_ + n + i] = g_H2[(size_t)(L_ - 1) * n + i];
    }
}

// ---------------------------------------------------------------------------
extern "C" void kernel_launch(void* const* d_in, const int* in_sizes, int n_in,
                              void* d_out, int out_size) {
    const float* x    = (const float*)d_in[0];
    const float* h1i  = (const float*)d_in[1];
    const float* h2i  = (const float*)d_in[2];
    const float* Wih1 = (const float*)d_in[3];
    const float* Whh1 = (const float*)d_in[4];
    const float* bih1 = (const float*)d_in[5];
    const float* bhh1 = (const float*)d_in[6];
    const float* Wih2 = (const float*)d_in[7];
    const float* Whh2 = (const float*)d_in[8];
    const float* bih2 = (const float*)d_in[9];
    const float* bhh2 = (const float*)d_in[10];
    const float* Wfc  = (const float*)d_in[11];
    const float* bfc  = (const float*)d_in[12];
    float* out = (float*)d_out;

    cudaFuncSetAttribute(k_steps, cudaFuncAttributeMaxDynamicSharedMemorySize, SMTOT_);

    void* bar_addr = nullptr;
    cudaGetSymbolAddress(&bar_addr, g_bars);
    cudaMemsetAsync(bar_addr, 0, 512 * sizeof(unsigned));

    k_prep_w<<<(G3_ * H_ + 255) / 256, 256>>>(Wih1, Whh1, Wih2, Whh2);
    k_prep_h<<<(B_ * H_ + 255) / 256, 256>>>(h1i, h2i);
    k_prep_x<<<(L_ * B_ * H_ + 255) / 256, 256>>>(x);

    k_steps<<<128, 512, SMTOT_>>>(h1i, h2i, bih1, bhh1, bih2, bhh2);

    k_fc<<<4096, 256>>>(Wfc, bfc, out);
    k_copy<<<(B_ * H_ + 255) / 256, 256>>>(out);
}

// round 16
// speedup vs baseline: 1.3309x; 1.3309x over previous
#include <cuda_runtime.h>
#include <cuda_fp16.h>
#include <math.h>
#include <stdint.h>

#define B_  512
#define T_  512
#define L_  64
#define H_  512
#define G3_ 1536
#define XW_ 575

#define SLOT_  61440
#define SMTOT_ 122880

// ------------------------- device scratch (no allocs) -----------------------
__device__ __align__(16) float g_H1fin[(size_t)B_ * H_];
__device__ __align__(16) float g_H2[(size_t)L_ * B_ * H_];
__device__ __align__(16) __half g_X2[(size_t)L_ * B_ * 1024];   // [t][b][hi|lo]
__device__ __align__(16) __half g_W0h[(size_t)G3_ * H_];
__device__ __align__(16) __half g_W1h[(size_t)G3_ * H_];
__device__ __align__(16) __half g_W2h[(size_t)G3_ * H_];
__device__ __align__(16) __half g_W3h[(size_t)G3_ * H_];
__device__ __align__(16) __half g_H1h[2][(size_t)B_ * H_], g_H1l[2][(size_t)B_ * H_];
__device__ __align__(16) __half g_H2h[2][(size_t)B_ * H_], g_H2l[2][(size_t)B_ * H_];
__device__ unsigned g_bars[512];

__device__ __forceinline__ float sigm(float v) { return 1.f / (1.f + __expf(-v)); }

__device__ __forceinline__ uint32_t smem_u32(const void* p) {
    uint32_t a;
    asm("{ .reg .u64 t; cvta.to.shared.u64 t, %1; cvt.u32.u64 %0, t; }" : "=r"(a) : "l"(p));
    return a;
}
__device__ __forceinline__ void ldsm4(uint32_t* r, uint32_t addr) {
    asm volatile("ldmatrix.sync.aligned.m8n8.x4.shared.b16 {%0,%1,%2,%3}, [%4];"
                 : "=r"(r[0]), "=r"(r[1]), "=r"(r[2]), "=r"(r[3]) : "r"(addr));
}
__device__ __forceinline__ void mma16816(float* c, const uint32_t* a, uint32_t b0, uint32_t b1) {
    asm volatile("mma.sync.aligned.m16n8k16.row.col.f32.f16.f16.f32 "
                 "{%0,%1,%2,%3}, {%4,%5,%6,%7}, {%8,%9}, {%0,%1,%2,%3};"
                 : "+f"(c[0]), "+f"(c[1]), "+f"(c[2]), "+f"(c[3])
                 : "r"(a[0]), "r"(a[1]), "r"(a[2]), "r"(a[3]), "r"(b0), "r"(b1));
}
__device__ __forceinline__ void split2h(float a, __half& h, __half& l) {
    h = __float2half_rn(a);
    l = __float2half_rn(a - __half2float(h));
}
__device__ __forceinline__ void cp16(uint32_t dst, const void* src) {
    asm volatile("cp.async.cg.shared.global [%0], [%1], 16;" :: "r"(dst), "l"(src));
}
__device__ __forceinline__ void cp_commit() {
    asm volatile("cp.async.commit_group;" ::: "memory");
}
template <int N> __device__ __forceinline__ void cp_wait() {
    asm volatile("cp.async.wait_group %0;" :: "n"(N) : "memory");
}
__device__ __forceinline__ void stage_cp(uint32_t dst, const __half* src,
                                         int rows, int stride, int tid, int nthr) {
    for (int i = tid; i < rows * 4; i += nthr) {
        int r = i >> 2, q = i & 3;
        cp16(dst + r * 80 + q * 16, src + (size_t)r * stride + q * 8);
    }
}

// ---------------------------------------------------------------------------
// Prep kernels
// ---------------------------------------------------------------------------
__global__ __launch_bounds__(256) void k_prep_w(const float* __restrict__ W0,
                                                const float* __restrict__ W1,
                                                const float* __restrict__ W2,
                                                const float* __restrict__ W3) {
    size_t i = (size_t)blockIdx.x * 256 + threadIdx.x;
    if (i >= (size_t)G3_ * H_) return;
    g_W0h[i] = __float2half_rn(W0[i]);
    g_W1h[i] = __float2half_rn(W1[i]);
    g_W2h[i] = __float2half_rn(W2[i]);
    g_W3h[i] = __float2half_rn(W3[i]);
}

__global__ __launch_bounds__(256) void k_prep_h(const float* __restrict__ h1i,
                                                const float* __restrict__ h2i) {
    size_t i = (size_t)blockIdx.x * 256 + threadIdx.x;
    if (i >= (size_t)B_ * H_) return;
    __half h, l;
    split2h(h1i[i], h, l); g_H1h[1][i] = h; g_H1l[1][i] = l;
    split2h(h2i[i], h, l); g_H2h[1][i] = h; g_H2l[1][i] = l;
}

__global__ __launch_bounds__(256) void k_prep_x(const float* __restrict__ x) {
    size_t i = (size_t)blockIdx.x * 256 + threadIdx.x;
    if (i >= (size_t)L_ * B_ * H_) return;
    int k = (int)(i % H_);
    int b = (int)((i / H_) % B_);
    int t = (int)(i / ((size_t)B_ * H_));
    __half h, l;
    split2h(x[(size_t)b * XW_ + t + k], h, l);
    size_t o = ((size_t)t * B_ + b) * 1024;
    g_X2[o + k] = h; g_X2[o + 512 + k] = l;
}

// ---------------------------------------------------------------------------
// k_steps: persistent recurrence, 4-way matmul warp specialization (round-12
// structure), fp16 numerics: A = hi+lo split (exact to 2^-22), W = single
// fp16 (quantization 2^-12 -> predicted final rel_err ~2-3e-4).
// Groups (4 warps, tile m32 x n16): G0: W_hh1@h1old; G1: W_ih2@h1old;
// G2: W_hh2@h2old; G3: W_ih1@x(i).
// Ring: 2 slots x 61440B. Slot: A1h@0 A1l@5120 A2h@10240 A2l@15360
//   AXh@20480 AXl@25600 | W@30720 + grp*7680 (3 gates x 2560).
// EX1 (G1->G2) @ slot0 A-region, EX2 (G3->G0) @ slot1 A-region.
// One per-m-group barrier per iteration.
// ---------------------------------------------------------------------------
__global__ __launch_bounds__(512, 1) void k_steps(const float* __restrict__ h1i,
                                                  const float* __restrict__ h2i,
                                                  const float* __restrict__ bih1,
                                                  const float* __restrict__ bhh1,
                                                  const float* __restrict__ bih2,
                                                  const float* __restrict__ bhh2) {
    extern __shared__ char sm[];
    const uint32_t smb = smem_u32(sm);
    const int tid = threadIdx.x;
    const int bid = blockIdx.x;
    const int j0 = (bid & 15) * 32;
    const int m0 = (bid >> 4) * 64;
    const int grp = bid >> 4;
    const int wid = tid >> 5, lane = tid & 31;
    const int group = wid >> 2;            // 0:W1, 1:W2, 2:W3, 3:W0(gi)
    const int wg = wid & 3;
    const int wm = (wg & 1) * 32;
    const int wn16 = (wg >> 1) * 16;
    const int arow = lane & 15, acol = (lane >> 4) * 8;
    const int brow = (lane & 7) + ((lane >> 4) << 3), bcol = ((lane >> 3) & 1) * 8;
    const int row = lane >> 2, colp = (lane & 3) * 2;

    // biases per group
    float2 bs0[2], bs1[2], bs2[2], bs3[2];
    float2 hp[2][2][2];   // G0 -> h1 carry, G2 -> h2 carry
#pragma unroll
    for (int nf = 0; nf < 2; nf++) {
        int jg = j0 + wn16 + nf * 8 + colp;
        float2 u, v;
        if (group == 0) {
            u = *(const float2*)(bih1 + jg);        v = *(const float2*)(bhh1 + jg);
            bs0[nf] = make_float2(u.x + v.x, u.y + v.y);
            u = *(const float2*)(bih1 + 512 + jg);  v = *(const float2*)(bhh1 + 512 + jg);
            bs1[nf] = make_float2(u.x + v.x, u.y + v.y);
            bs2[nf] = *(const float2*)(bih1 + 1024 + jg);
            bs3[nf] = *(const float2*)(bhh1 + 1024 + jg);
        } else if (group == 2) {
            u = *(const float2*)(bih2 + jg);        v = *(const float2*)(bhh2 + jg);
            bs0[nf] = make_float2(u.x + v.x, u.y + v.y);
            u = *(const float2*)(bih2 + 512 + jg);  v = *(const float2*)(bhh2 + 512 + jg);
            bs1[nf] = make_float2(u.x + v.x, u.y + v.y);
            bs2[nf] = *(const float2*)(bih2 + 1024 + jg);
            bs3[nf] = *(const float2*)(bhh2 + 1024 + jg);
        } else {
            bs0[nf] = bs1[nf] = bs2[nf] = bs3[nf] = make_float2(0.f, 0.f);
        }
#pragma unroll
        for (int mf = 0; mf < 2; mf++)
#pragma unroll
            for (int hh = 0; hh < 2; hh++) {
                int m = m0 + wm + mf * 16 + row + hh * 8;
                const float* src = (group == 2) ? h2i : h1i;
                hp[mf][nf][hh] = *(const float2*)(src + (size_t)m * H_ + jg);
            }
    }

    auto stageW = [&](int c) {
        const int k0 = c * 32;
        uint32_t d = smb + (uint32_t)(c & 1) * SLOT_ + 30720u;
#pragma unroll
        for (int g = 0; g < 3; g++) {
            const size_t wo = (size_t)(g * 512 + j0) * H_ + k0;
            stage_cp(d +     0 + g * 2560, g_W1h + wo, 32, H_, tid, 512);
            stage_cp(d +  7680 + g * 2560, g_W2h + wo, 32, H_, tid, 512);
            stage_cp(d + 15360 + g * 2560, g_W3h + wo, 32, H_, tid, 512);
            stage_cp(d + 23040 + g * 2560, g_W0h + wo, 32, H_, tid, 512);
        }
    };
    auto stageA = [&](int c, int op1, int op2, int ti) {
        const int k0 = c * 32;
        uint32_t d = smb + (uint32_t)(c & 1) * SLOT_;
        stage_cp(d,         g_H1h[op1] + (size_t)m0 * H_ + k0, 64, H_, tid, 512);
        stage_cp(d + 5120,  g_H1l[op1] + (size_t)m0 * H_ + k0, 64, H_, tid, 512);
        stage_cp(d + 10240, g_H2h[op2] + (size_t)m0 * H_ + k0, 64, H_, tid, 512);
        stage_cp(d + 15360, g_H2l[op2] + (size_t)m0 * H_ + k0, 64, H_, tid, 512);
        const __half* X = g_X2 + ((size_t)ti * B_ + m0) * 1024;
        stage_cp(d + 20480, X + k0,       64, 1024, tid, 512);
        stage_cp(d + 25600, X + 512 + k0, 64, 1024, tid, 512);
    };

    const uint32_t abase_off = (group == 2) ? 10240u : ((group == 3) ? 20480u : 0u);
    const uint32_t wbase_off = 30720u + (uint32_t)group * 7680u;
    const uint32_t ex1 = smb;            // slot0 A-region (G1 -> G2)
    const uint32_t ex2 = smb + SLOT_;    // slot1 A-region (G3 -> G0)
    const int exi = ((wg * 32 + lane) * 48) * 4;

    // bootstrap: chunk-0 weights
    stageW(0); cp_commit();

    unsigned barT = 0;
    for (int i = 0; i <= L_; i++) {
        const int op1 = (i + 1) & 1;
        const int op2 = i & 1;
        const int ti = (i < L_) ? i : 0;

        stageA(0, op1, op2, ti); cp_commit();

        float acc[3][2][2][4];
#pragma unroll
        for (int g = 0; g < 3; g++)
#pragma unroll
            for (int mf = 0; mf < 2; mf++)
#pragma unroll
                for (int nf = 0; nf < 2; nf++)
#pragma unroll
                    for (int q = 0; q < 4; q++) acc[g][mf][nf][q] = 0.f;

        for (int gc = 0; gc < 16; gc++) {
            cp_wait<0>();
            __syncthreads();
            if (gc + 1 < 16) { stageW(gc + 1); stageA(gc + 1, op1, op2, ti); }
            cp_commit();
            const uint32_t Ab = smb + (uint32_t)(gc & 1) * SLOT_;
            const uint32_t abase = Ab + abase_off;
            const uint32_t wbase = Ab + wbase_off;
#pragma unroll
            for (int h = 0; h < 2; h++) {
                const int c0 = h * 16;
                uint32_t aH[2][4], aL[2][4];
#pragma unroll
                for (int mf = 0; mf < 2; mf++) {
                    uint32_t ao = ((wm + mf * 16 + arow) * 40 + c0 + acol) * 2;
                    ldsm4(aH[mf], abase + ao);
                    ldsm4(aL[mf], abase + 5120 + ao);
                }
                const uint32_t bo = ((wn16 + brow) * 40 + c0 + bcol) * 2;
#pragma unroll
                for (int g = 0; g < 3; g++) {
                    uint32_t bh[4];
                    ldsm4(bh, wbase + g * 2560 + bo);
#pragma unroll
                    for (int mf = 0; mf < 2; mf++)
#pragma unroll
                        for (int nf = 0; nf < 2; nf++) {
                            float* a = acc[g][mf][nf];
                            mma16816(a, aH[mf], bh[nf * 2], bh[nf * 2 + 1]);
                            mma16816(a, aL[mf], bh[nf * 2], bh[nf * 2 + 1]);
                        }
                }
            }
        }
        cp_wait<0>();
        __syncthreads();   // all ldsm done; A-regions now dead -> exchanges

        if (group == 1) {
#pragma unroll
            for (int g = 0; g < 3; g++)
#pragma unroll
                for (int mf = 0; mf < 2; mf++)
#pragma unroll
                    for (int nf = 0; nf < 2; nf++)
#pragma unroll
                        for (int q = 0; q < 4; q++) {
                            uint32_t addr = ex1 + exi + (((g * 2 + mf) * 2 + nf) * 4 + q) * 4;
                            asm volatile("st.shared.f32 [%0], %1;" :: "r"(addr), "f"(acc[g][mf][nf][q]));
                        }
        }
        if (group == 3) {
#pragma unroll
            for (int g = 0; g < 3; g++)
#pragma unroll
                for (int mf = 0; mf < 2; mf++)
#pragma unroll
                    for (int nf = 0; nf < 2; nf++)
#pragma unroll
                        for (int q = 0; q < 4; q++) {
                            uint32_t addr = ex2 + exi + (((g * 2 + mf) * 2 + nf) * 4 + q) * 4;
                            asm volatile("st.shared.f32 [%0], %1;" :: "r"(addr), "f"(acc[g][mf][nf][q]));
                        }
        }
        // prestage next iteration's chunk-0 weights (slot0 W region is dead)
        if (i < L_) { stageW(0); cp_commit(); }
        __syncthreads();   // exchanges visible

        // ---- G0: layer-1 epilogue -> h1(i), consuming G3's gi accumulators ----
        if (group == 0 && i < L_) {
            __half* hhN = g_H1h[i & 1];
            __half* hlN = g_H1l[i & 1];
#pragma unroll
            for (int mf = 0; mf < 2; mf++)
#pragma unroll
                for (int nf = 0; nf < 2; nf++) {
                    int jg = j0 + wn16 + nf * 8 + colp;
#pragma unroll
                    for (int hh = 0; hh < 2; hh++) {
                        int m = m0 + wm + mf * 16 + row + hh * 8;
                        float exv[6];
#pragma unroll
                        for (int g = 0; g < 3; g++)
#pragma unroll
                            for (int q = 0; q < 2; q++) {
                                uint32_t addr = ex2 + exi + (((g * 2 + mf) * 2 + nf) * 4 + hh * 2 + q) * 4;
                                asm volatile("ld.shared.f32 %0, [%1];" : "=f"(exv[g * 2 + q]) : "r"(addr));
                            }
                        float r0 = sigm(exv[0] + acc[0][mf][nf][hh * 2] + bs0[nf].x);
                        float r1 = sigm(exv[1] + acc[0][mf][nf][hh * 2 + 1] + bs0[nf].y);
                        float z0 = sigm(exv[2] + acc[1][mf][nf][hh * 2] + bs1[nf].x);
                        float z1 = sigm(exv[3] + acc[1][mf][nf][hh * 2 + 1] + bs1[nf].y);
                        float n0 = tanhf(exv[4] + bs2[nf].x + r0 * (acc[2][mf][nf][hh * 2] + bs3[nf].x));
                        float n1 = tanhf(exv[5] + bs2[nf].y + r1 * (acc[2][mf][nf][hh * 2 + 1] + bs3[nf].y));
                        float h0 = (1.f - z0) * n0 + z0 * hp[mf][nf][hh].x;
                        float h1 = (1.f - z1) * n1 + z1 * hp[mf][nf][hh].y;
                        hp[mf][nf][hh] = make_float2(h0, h1);
                        __half x0, y0, x1, y1;
                        split2h(h0, x0, y0); split2h(h1, x1, y1);
                        __half2 hv; hv.x = x0; hv.y = x1;
                        __half2 lv; lv.x = y0; lv.y = y1;
                        *(__half2*)(hhN + (size_t)m * H_ + jg) = hv;
                        *(__half2*)(hlN + (size_t)m * H_ + jg) = lv;
                        if (i == L_ - 1)
                            *(float2*)(g_H1fin + (size_t)m * H_ + jg) = make_float2(h0, h1);
                    }
                }
        }

        // ---- G2: layer-2 epilogue -> h2(i-1), consuming G1's gi2 accumulators ----
        if (group == 2 && i > 0) {
            const int t2 = i - 1;
            float* h2new = g_H2 + (size_t)t2 * B_ * H_;
            __half* hhN = g_H2h[t2 & 1];
            __half* hlN = g_H2l[t2 & 1];
#pragma unroll
            for (int mf = 0; mf < 2; mf++)
#pragma unroll
                for (int nf = 0; nf < 2; nf++) {
                    int jg = j0 + wn16 + nf * 8 + colp;
#pragma unroll
                    for (int hh = 0; hh < 2; hh++) {
                        int m = m0 + wm + mf * 16 + row + hh * 8;
                        float exv[6];
#pragma unroll
                        for (int g = 0; g < 3; g++)
#pragma unroll
                            for (int q = 0; q < 2; q++) {
                                uint32_t addr = ex1 + exi + (((g * 2 + mf) * 2 + nf) * 4 + hh * 2 + q) * 4;
                                asm volatile("ld.shared.f32 %0, [%1];" : "=f"(exv[g * 2 + q]) : "r"(addr));
                            }
                        float r0 = sigm(acc[0][mf][nf][hh * 2] + exv[0] + bs0[nf].x);
                        float r1 = sigm(acc[0][mf][nf][hh * 2 + 1] + exv[1] + bs0[nf].y);
                        float z0 = sigm(acc[1][mf][nf][hh * 2] + exv[2] + bs1[nf].x);
                        float z1 = sigm(acc[1][mf][nf][hh * 2 + 1] + exv[3] + bs1[nf].y);
                        float n0 = tanhf(exv[4] + bs2[nf].x + r0 * (acc[2][mf][nf][hh * 2] + bs3[nf].x));
                        float n1 = tanhf(exv[5] + bs2[nf].y + r1 * (acc[2][mf][nf][hh * 2 + 1] + bs3[nf].y));
                        float h0 = (1.f - z0) * n0 + z0 * hp[mf][nf][hh].x;
                        float h1 = (1.f - z1) * n1 + z1 * hp[mf][nf][hh].y;
                        hp[mf][nf][hh] = make_float2(h0, h1);
                        *(float2*)(h2new + (size_t)m * H_ + jg) = make_float2(h0, h1);
                        __half x0, y0, x1, y1;
                        split2h(h0, x0, y0); split2h(h1, x1, y1);
                        __half2 hv; hv.x = x0; hv.y = x1;
                        __half2 lv; lv.x = y0; lv.y = y1;
                        *(__half2*)(hhN + (size_t)m * H_ + jg) = hv;
                        *(__half2*)(hlN + (size_t)m * H_ + jg) = lv;
                    }
                }
        }

        // ---- per-m-group barrier ----
        __threadfence();
        __syncthreads();
        if (tid == 0) atomicAdd(&g_bars[grp * 32], 1u);
        barT += 16;
        if (tid == 0) {
            while (*(volatile unsigned*)&g_bars[grp * 32] < barT) { }
        }
        __syncthreads();
    }
}

// ---------------------------------------------------------------------------
__global__ __launch_bounds__(256) void k_fc(const float* __restrict__ Wfc,
                                            const float* __restrict__ bfc,
                                            float* __restrict__ out) {
    int w = (blockIdx.x * 256 + threadIdx.x) >> 5;
    int lane = threadIdx.x & 31;
    int b = w >> 6, tt = w & 63;
    const float* h = g_H2 + ((size_t)tt * B_ + b) * H_;
    float s = 0.f;
#pragma unroll
    for (int q = 0; q < H_ / 32; q++) s += h[lane + 32 * q] * Wfc[lane + 32 * q];
#pragma unroll
    for (int off = 16; off; off >>= 1) s += __shfl_down_sync(0xffffffffu, s, off);
    if (lane == 0) out[(size_t)b * L_ + tt] = s + bfc[0];
}

__global__ __launch_bounds__(256) void k_copy(float* __restrict__ out) {
    int i = blockIdx.x * 256 + threadIdx.x;
    const int n = B_ * H_;
    if (i < n) {
        out[B_ * L_ + i] = g_H1fin[i];
        out[B_ * L_ + n + i] = g_H2[(size_t)(L_ - 1) * n + i];
    }
}

// ---------------------------------------------------------------------------
extern "C" void kernel_launch(void* const* d_in, const int* in_sizes, int n_in,
                              void* d_out, int out_size) {
    const float* x    = (const float*)d_in[0];
    const float* h1i  = (const float*)d_in[1];
    const float* h2i  = (const float*)d_in[2];
    const float* Wih1 = (const float*)d_in[3];
    const float* Whh1 = (const float*)d_in[4];
    const float* bih1 = (const float*)d_in[5];
    const float* bhh1 = (const float*)d_in[6];
    const float* Wih2 = (const float*)d_in[7];
    const float* Whh2 = (const float*)d_in[8];
    const float* bih2 = (const float*)d_in[9];
    const float* bhh2 = (const float*)d_in[10];
    const float* Wfc  = (const float*)d_in[11];
    const float* bfc  = (const float*)d_in[12];
    float* out = (float*)d_out;

    cudaFuncSetAttribute(k_steps, cudaFuncAttributeMaxDynamicSharedMemorySize, SMTOT_);

    void* bar_addr = nullptr;
    cudaGetSymbolAddress(&bar_addr, g_bars);
    cudaMemsetAsync(bar_addr, 0, 512 * sizeof(unsigned));

    k_prep_w<<<(G3_ * H_ + 255) / 256, 256>>>(Wih1, Whh1, Wih2, Whh2);
    k_prep_h<<<(B_ * H_ + 255) / 256, 256>>>(h1i, h2i);
    k_prep_x<<<(L_ * B_ * H_ + 255) / 256, 256>>>(x);

    k_steps<<<128, 512, SMTOT_>>>(h1i, h2i, bih1, bhh1, bih2, bhh2);

    k_fc<<<4096, 256>>>(Wfc, bfc, out);
    k_copy<<<(B_ * H_ + 255) / 256, 256>>>(out);
}

// round 17
// speedup vs baseline: 1.3452x; 1.0107x over previous
#include <cuda_runtime.h>
#include <cuda_fp16.h>
#include <math.h>
#include <stdint.h>

#define B_  512
#define T_  512
#define L_  64
#define H_  512
#define G3_ 1536
#define XW_ 575

#define SLOT_  61440
#define SMTOT_ 184320

// ------------------------- device scratch (no allocs) -----------------------
__device__ __align__(16) float g_H1fin[(size_t)B_ * H_];
__device__ __align__(16) float g_H2[(size_t)L_ * B_ * H_];
__device__ __align__(16) __half g_X2[(size_t)L_ * B_ * 1024];   // [t][b][hi|lo]
__device__ __align__(16) __half g_W0h[(size_t)G3_ * H_];
__device__ __align__(16) __half g_W1h[(size_t)G3_ * H_];
__device__ __align__(16) __half g_W2h[(size_t)G3_ * H_];
__device__ __align__(16) __half g_W3h[(size_t)G3_ * H_];
__device__ __align__(16) __half g_H1h[2][(size_t)B_ * H_], g_H1l[2][(size_t)B_ * H_];
__device__ __align__(16) __half g_H2h[2][(size_t)B_ * H_], g_H2l[2][(size_t)B_ * H_];
__device__ unsigned g_bars[512];

__device__ __forceinline__ float sigm(float v) { return 1.f / (1.f + __expf(-v)); }

__device__ __forceinline__ uint32_t smem_u32(const void* p) {
    uint32_t a;
    asm("{ .reg .u64 t; cvta.to.shared.u64 t, %1; cvt.u32.u64 %0, t; }" : "=r"(a) : "l"(p));
    return a;
}
__device__ __forceinline__ void ldsm4(uint32_t* r, uint32_t addr) {
    asm volatile("ldmatrix.sync.aligned.m8n8.x4.shared.b16 {%0,%1,%2,%3}, [%4];"
                 : "=r"(r[0]), "=r"(r[1]), "=r"(r[2]), "=r"(r[3]) : "r"(addr));
}
__device__ __forceinline__ void mma16816(float* c, const uint32_t* a, uint32_t b0, uint32_t b1) {
    asm volatile("mma.sync.aligned.m16n8k16.row.col.f32.f16.f16.f32 "
                 "{%0,%1,%2,%3}, {%4,%5,%6,%7}, {%8,%9}, {%0,%1,%2,%3};"
                 : "+f"(c[0]), "+f"(c[1]), "+f"(c[2]), "+f"(c[3])
                 : "r"(a[0]), "r"(a[1]), "r"(a[2]), "r"(a[3]), "r"(b0), "r"(b1));
}
__device__ __forceinline__ void split2h(float a, __half& h, __half& l) {
    h = __float2half_rn(a);
    l = __float2half_rn(a - __half2float(h));
}
__device__ __forceinline__ void cp16(uint32_t dst, const void* src) {
    asm volatile("cp.async.cg.shared.global [%0], [%1], 16;" :: "r"(dst), "l"(src));
}
__device__ __forceinline__ void cp_commit() {
    asm volatile("cp.async.commit_group;" ::: "memory");
}
template <int N> __device__ __forceinline__ void cp_wait() {
    asm volatile("cp.async.wait_group %0;" :: "n"(N) : "memory");
}
__device__ __forceinline__ void stage_cp(uint32_t dst, const __half* src,
                                         int rows, int stride, int tid, int nthr) {
    for (int i = tid; i < rows * 4; i += nthr) {
        int r = i >> 2, q = i & 3;
        cp16(dst + r * 80 + q * 16, src + (size_t)r * stride + q * 8);
    }
}

// ---------------------------------------------------------------------------
// Prep kernels
// ---------------------------------------------------------------------------
__global__ __launch_bounds__(256) void k_prep_w(const float* __restrict__ W0,
                                                const float* __restrict__ W1,
                                                const float* __restrict__ W2,
                                                const float* __restrict__ W3) {
    size_t i = (size_t)blockIdx.x * 256 + threadIdx.x;
    if (i >= (size_t)G3_ * H_) return;
    g_W0h[i] = __float2half_rn(W0[i]);
    g_W1h[i] = __float2half_rn(W1[i]);
    g_W2h[i] = __float2half_rn(W2[i]);
    g_W3h[i] = __float2half_rn(W3[i]);
}

__global__ __launch_bounds__(256) void k_prep_h(const float* __restrict__ h1i,
                                                const float* __restrict__ h2i) {
    size_t i = (size_t)blockIdx.x * 256 + threadIdx.x;
    if (i >= (size_t)B_ * H_) return;
    __half h, l;
    split2h(h1i[i], h, l); g_H1h[1][i] = h; g_H1l[1][i] = l;
    split2h(h2i[i], h, l); g_H2h[1][i] = h; g_H2l[1][i] = l;
}

__global__ __launch_bounds__(256) void k_prep_x(const float* __restrict__ x) {
    size_t i = (size_t)blockIdx.x * 256 + threadIdx.x;
    if (i >= (size_t)L_ * B_ * H_) return;
    int k = (int)(i % H_);
    int b = (int)((i / H_) % B_);
    int t = (int)(i / ((size_t)B_ * H_));
    __half h, l;
    split2h(x[(size_t)b * XW_ + t + k], h, l);
    size_t o = ((size_t)t * B_ + b) * 1024;
    g_X2[o + k] = h; g_X2[o + 512 + k] = l;
}

// ---------------------------------------------------------------------------
// k_steps: persistent recurrence, 4-way matmul warp specialization, fp16
// 2-term numerics (A hi/lo split, W single fp16). NEW: 3-slot cp.async ring
// (slot = gc%3) with lookahead-1 (wait<1>) so one chunk's DMA latency is
// always off the critical path. Conditional commits keep group accounting
// exact; last chunk uses wait<0>.
// Groups (4 warps, tile m32 x n16): G0: W_hh1@h1old; G1: W_ih2@h1old;
// G2: W_hh2@h2old; G3: W_ih1@x(i).
// Slot: A1h@0 A1l@5120 A2h@10240 A2l@15360 AXh@20480 AXl@25600
//       W@30720 + grp*7680 (3 gates x 2560).
// EX1 (G1->G2) @ slot0 A-region, EX2 (G3->G0) @ slot1 A-region.
// W(0)/W(1) prestaged into slots 0/1 at iter end (step-invariant);
// only A(0)/A(1) staged after the barrier.
// ---------------------------------------------------------------------------
__global__ __launch_bounds__(512, 1) void k_steps(const float* __restrict__ h1i,
                                                  const float* __restrict__ h2i,
                                                  const float* __restrict__ bih1,
                                                  const float* __restrict__ bhh1,
                                                  const float* __restrict__ bih2,
                                                  const float* __restrict__ bhh2) {
    extern __shared__ char sm[];
    const uint32_t smb = smem_u32(sm);
    const int tid = threadIdx.x;
    const int bid = blockIdx.x;
    const int j0 = (bid & 15) * 32;
    const int m0 = (bid >> 4) * 64;
    const int grp = bid >> 4;
    const int wid = tid >> 5, lane = tid & 31;
    const int group = wid >> 2;            // 0:W1, 1:W2, 2:W3, 3:W0(gi)
    const int wg = wid & 3;
    const int wm = (wg & 1) * 32;
    const int wn16 = (wg >> 1) * 16;
    const int arow = lane & 15, acol = (lane >> 4) * 8;
    const int brow = (lane & 7) + ((lane >> 4) << 3), bcol = ((lane >> 3) & 1) * 8;
    const int row = lane >> 2, colp = (lane & 3) * 2;

    // biases per group
    float2 bs0[2], bs1[2], bs2[2], bs3[2];
    float2 hp[2][2][2];   // G0 -> h1 carry, G2 -> h2 carry
#pragma unroll
    for (int nf = 0; nf < 2; nf++) {
        int jg = j0 + wn16 + nf * 8 + colp;
        float2 u, v;
        if (group == 0) {
            u = *(const float2*)(bih1 + jg);        v = *(const float2*)(bhh1 + jg);
            bs0[nf] = make_float2(u.x + v.x, u.y + v.y);
            u = *(const float2*)(bih1 + 512 + jg);  v = *(const float2*)(bhh1 + 512 + jg);
            bs1[nf] = make_float2(u.x + v.x, u.y + v.y);
            bs2[nf] = *(const float2*)(bih1 + 1024 + jg);
            bs3[nf] = *(const float2*)(bhh1 + 1024 + jg);
        } else if (group == 2) {
            u = *(const float2*)(bih2 + jg);        v = *(const float2*)(bhh2 + jg);
            bs0[nf] = make_float2(u.x + v.x, u.y + v.y);
            u = *(const float2*)(bih2 + 512 + jg);  v = *(const float2*)(bhh2 + 512 + jg);
            bs1[nf] = make_float2(u.x + v.x, u.y + v.y);
            bs2[nf] = *(const float2*)(bih2 + 1024 + jg);
            bs3[nf] = *(const float2*)(bhh2 + 1024 + jg);
        } else {
            bs0[nf] = bs1[nf] = bs2[nf] = bs3[nf] = make_float2(0.f, 0.f);
        }
#pragma unroll
        for (int mf = 0; mf < 2; mf++)
#pragma unroll
            for (int hh = 0; hh < 2; hh++) {
                int m = m0 + wm + mf * 16 + row + hh * 8;
                const float* src = (group == 2) ? h2i : h1i;
                hp[mf][nf][hh] = *(const float2*)(src + (size_t)m * H_ + jg);
            }
    }

    auto stageW = [&](int c) {
        const int k0 = c * 32;
        uint32_t d = smb + (uint32_t)(c % 3) * SLOT_ + 30720u;
#pragma unroll
        for (int g = 0; g < 3; g++) {
            const size_t wo = (size_t)(g * 512 + j0) * H_ + k0;
            stage_cp(d +     0 + g * 2560, g_W1h + wo, 32, H_, tid, 512);
            stage_cp(d +  7680 + g * 2560, g_W2h + wo, 32, H_, tid, 512);
            stage_cp(d + 15360 + g * 2560, g_W3h + wo, 32, H_, tid, 512);
            stage_cp(d + 23040 + g * 2560, g_W0h + wo, 32, H_, tid, 512);
        }
    };
    auto stageA = [&](int c, int op1, int op2, int ti) {
        const int k0 = c * 32;
        uint32_t d = smb + (uint32_t)(c % 3) * SLOT_;
        stage_cp(d,         g_H1h[op1] + (size_t)m0 * H_ + k0, 64, H_, tid, 512);
        stage_cp(d + 5120,  g_H1l[op1] + (size_t)m0 * H_ + k0, 64, H_, tid, 512);
        stage_cp(d + 10240, g_H2h[op2] + (size_t)m0 * H_ + k0, 64, H_, tid, 512);
        stage_cp(d + 15360, g_H2l[op2] + (size_t)m0 * H_ + k0, 64, H_, tid, 512);
        const __half* X = g_X2 + ((size_t)ti * B_ + m0) * 1024;
        stage_cp(d + 20480, X + k0,       64, 1024, tid, 512);
        stage_cp(d + 25600, X + 512 + k0, 64, 1024, tid, 512);
    };

    const uint32_t abase_off = (group == 2) ? 10240u : ((group == 3) ? 20480u : 0u);
    const uint32_t wbase_off = 30720u + (uint32_t)group * 7680u;
    const uint32_t ex1 = smb;            // slot0 A-region (G1 -> G2)
    const uint32_t ex2 = smb + SLOT_;    // slot1 A-region (G3 -> G0)
    const int exi = ((wg * 32 + lane) * 48) * 4;

    // bootstrap: chunk-0,1 weights (slots 0,1) — one group (Gpre)
    stageW(0); stageW(1); cp_commit();

    unsigned barT = 0;
    for (int i = 0; i <= L_; i++) {
        const int op1 = (i + 1) & 1;
        const int op2 = i & 1;
        const int ti = (i < L_) ? i : 0;

        // barrier-dependent staging: A-panels of chunks 0,1
        stageA(0, op1, op2, ti); cp_commit();
        stageA(1, op1, op2, ti); cp_commit();

        float acc[3][2][2][4];
#pragma unroll
        for (int g = 0; g < 3; g++)
#pragma unroll
            for (int mf = 0; mf < 2; mf++)
#pragma unroll
                for (int nf = 0; nf < 2; nf++)
#pragma unroll
                    for (int q = 0; q < 4; q++) acc[g][mf][nf][q] = 0.f;

        // group queue per iter: Gpre{W0,W1}, {A0}, {A1}, {W2,A2}, ..., {W15,A15}
        // chunk gc needs groups up through index gc+1 complete -> wait<1>,
        // except the final chunk which needs everything -> wait<0>.
        for (int gc = 0; gc < 16; gc++) {
            if (gc == 15) cp_wait<0>(); else cp_wait<1>();
            __syncthreads();
            if (gc + 2 < 16) {
                stageW(gc + 2); stageA(gc + 2, op1, op2, ti);
                cp_commit();
            }
            const uint32_t Ab = smb + (uint32_t)(gc % 3) * SLOT_;
            const uint32_t abase = Ab + abase_off;
            const uint32_t wbase = Ab + wbase_off;
#pragma unroll
            for (int h = 0; h < 2; h++) {
                const int c0 = h * 16;
                uint32_t aH[2][4], aL[2][4];
#pragma unroll
                for (int mf = 0; mf < 2; mf++) {
                    uint32_t ao = ((wm + mf * 16 + arow) * 40 + c0 + acol) * 2;
                    ldsm4(aH[mf], abase + ao);
                    ldsm4(aL[mf], abase + 5120 + ao);
                }
                const uint32_t bo = ((wn16 + brow) * 40 + c0 + bcol) * 2;
#pragma unroll
                for (int g = 0; g < 3; g++) {
                    uint32_t bh[4];
                    ldsm4(bh, wbase + g * 2560 + bo);
#pragma unroll
                    for (int mf = 0; mf < 2; mf++)
#pragma unroll
                        for (int nf = 0; nf < 2; nf++) {
                            float* a = acc[g][mf][nf];
                            mma16816(a, aH[mf], bh[nf * 2], bh[nf * 2 + 1]);
                            mma16816(a, aL[mf], bh[nf * 2], bh[nf * 2 + 1]);
                        }
                }
            }
        }
        __syncthreads();   // all ldsm done; all slots dead -> exchanges

        if (group == 1) {
#pragma unroll
            for (int g = 0; g < 3; g++)
#pragma unroll
                for (int mf = 0; mf < 2; mf++)
#pragma unroll
                    for (int nf = 0; nf < 2; nf++)
#pragma unroll
                        for (int q = 0; q < 4; q++) {
                            uint32_t addr = ex1 + exi + (((g * 2 + mf) * 2 + nf) * 4 + q) * 4;
                            asm volatile("st.shared.f32 [%0], %1;" :: "r"(addr), "f"(acc[g][mf][nf][q]));
                        }
        }
        if (group == 3) {
#pragma unroll
            for (int g = 0; g < 3; g++)
#pragma unroll
                for (int mf = 0; mf < 2; mf++)
#pragma unroll
                    for (int nf = 0; nf < 2; nf++)
#pragma unroll
                        for (int q = 0; q < 4; q++) {
                            uint32_t addr = ex2 + exi + (((g * 2 + mf) * 2 + nf) * 4 + q) * 4;
                            asm volatile("st.shared.f32 [%0], %1;" :: "r"(addr), "f"(acc[g][mf][nf][q]));
                        }
        }
        // prestage next iteration's chunk-0,1 weights (W regions of slots 0,1
        // are dead; EX lives in A-regions — disjoint)
        if (i < L_) { stageW(0); stageW(1); cp_commit(); }
        __syncthreads();   // exchanges visible

        // ---- G0: layer-1 epilogue -> h1(i), consuming G3's gi accumulators ----
        if (group == 0 && i < L_) {
            __half* hhN = g_H1h[i & 1];
            __half* hlN = g_H1l[i & 1];
#pragma unroll
            for (int mf = 0; mf < 2; mf++)
#pragma unroll
                for (int nf = 0; nf < 2; nf++) {
                    int jg = j0 + wn16 + nf * 8 + colp;
#pragma unroll
                    for (int hh = 0; hh < 2; hh++) {
                        int m = m0 + wm + mf * 16 + row + hh * 8;
                        float exv[6];
#pragma unroll
                        for (int g = 0; g < 3; g++)
#pragma unroll
                            for (int q = 0; q < 2; q++) {
                                uint32_t addr = ex2 + exi + (((g * 2 + mf) * 2 + nf) * 4 + hh * 2 + q) * 4;
                                asm volatile("ld.shared.f32 %0, [%1];" : "=f"(exv[g * 2 + q]) : "r"(addr));
                            }
                        float r0 = sigm(exv[0] + acc[0][mf][nf][hh * 2] + bs0[nf].x);
                        float r1 = sigm(exv[1] + acc[0][mf][nf][hh * 2 + 1] + bs0[nf].y);
                        float z0 = sigm(exv[2] + acc[1][mf][nf][hh * 2] + bs1[nf].x);
                        float z1 = sigm(exv[3] + acc[1][mf][nf][hh * 2 + 1] + bs1[nf].y);
                        float n0 = tanhf(exv[4] + bs2[nf].x + r0 * (acc[2][mf][nf][hh * 2] + bs3[nf].x));
                        float n1 = tanhf(exv[5] + bs2[nf].y + r1 * (acc[2][mf][nf][hh * 2 + 1] + bs3[nf].y));
                        float h0 = (1.f - z0) * n0 + z0 * hp[mf][nf][hh].x;
                        float h1 = (1.f - z1) * n1 + z1 * hp[mf][nf][hh].y;
                        hp[mf][nf][hh] = make_float2(h0, h1);
                        __half x0, y0, x1, y1;
                        split2h(h0, x0, y0); split2h(h1, x1, y1);
                        __half2 hv; hv.x = x0; hv.y = x1;
                        __half2 lv; lv.x = y0; lv.y = y1;
                        *(__half2*)(hhN + (size_t)m * H_ + jg) = hv;
                        *(__half2*)(hlN + (size_t)m * H_ + jg) = lv;
                        if (i == L_ - 1)
                            *(float2*)(g_H1fin + (size_t)m * H_ + jg) = make_float2(h0, h1);
                    }
                }
        }

        // ---- G2: layer-2 epilogue -> h2(i-1), consuming G1's gi2 accumulators ----
        if (group == 2 && i > 0) {
            const int t2 = i - 1;
            float* h2new = g_H2 + (size_t)t2 * B_ * H_;
            __half* hhN = g_H2h[t2 & 1];
            __half* hlN = g_H2l[t2 & 1];
#pragma unroll
            for (int mf = 0; mf < 2; mf++)
#pragma unroll
                for (int nf = 0; nf < 2; nf++) {
                    int jg = j0 + wn16 + nf * 8 + colp;
#pragma unroll
                    for (int hh = 0; hh < 2; hh++) {
                        int m = m0 + wm + mf * 16 + row + hh * 8;
                        float exv[6];
#pragma unroll
                        for (int g = 0; g < 3; g++)
#pragma unroll
                            for (int q = 0; q < 2; q++) {
                                uint32_t addr = ex1 + exi + (((g * 2 + mf) * 2 + nf) * 4 + hh * 2 + q) * 4;
                                asm volatile("ld.shared.f32 %0, [%1];" : "=f"(exv[g * 2 + q]) : "r"(addr));
                            }
                        float r0 = sigm(acc[0][mf][nf][hh * 2] + exv[0] + bs0[nf].x);
                        float r1 = sigm(acc[0][mf][nf][hh * 2 + 1] + exv[1] + bs0[nf].y);
                        float z0 = sigm(acc[1][mf][nf][hh * 2] + exv[2] + bs1[nf].x);
                        float z1 = sigm(acc[1][mf][nf][hh * 2 + 1] + exv[3] + bs1[nf].y);
                        float n0 = tanhf(exv[4] + bs2[nf].x + r0 * (acc[2][mf][nf][hh * 2] + bs3[nf].x));
                        float n1 = tanhf(exv[5] + bs2[nf].y + r1 * (acc[2][mf][nf][hh * 2 + 1] + bs3[nf].y));
                        float h0 = (1.f - z0) * n0 + z0 * hp[mf][nf][hh].x;
                        float h1 = (1.f - z1) * n1 + z1 * hp[mf][nf][hh].y;
                        hp[mf][nf][hh] = make_float2(h0, h1);
                        *(float2*)(h2new + (size_t)m * H_ + jg) = make_float2(h0, h1);
                        __half x0, y0, x1, y1;
                        split2h(h0, x0, y0); split2h(h1, x1, y1);
                        __half2 hv; hv.x = x0; hv.y = x1;
                        __half2 lv; lv.x = y0; lv.y = y1;
                        *(__half2*)(hhN + (size_t)m * H_ + jg) = hv;
                        *(__half2*)(hlN + (size_t)m * H_ + jg) = lv;
                    }
                }
        }

        // ---- per-m-group barrier ----
        __threadfence();
        __syncthreads();
        if (tid == 0) atomicAdd(&g_bars[grp * 32], 1u);
        barT += 16;
        if (tid == 0) {
            while (*(volatile unsigned*)&g_bars[grp * 32] < barT) { }
        }
        __syncthreads();
    }
}

// ---------------------------------------------------------------------------
__global__ __launch_bounds__(256) void k_fc(const float* __restrict__ Wfc,
                                            const float* __restrict__ bfc,
                                            float* __restrict__ out) {
    int w = (blockIdx.x * 256 + threadIdx.x) >> 5;
    int lane = threadIdx.x & 31;
    int b = w >> 6, tt = w & 63;
    const float* h = g_H2 + ((size_t)tt * B_ + b) * H_;
    float s = 0.f;
#pragma unroll
    for (int q = 0; q < H_ / 32; q++) s += h[lane + 32 * q] * Wfc[lane + 32 * q];
#pragma unroll
    for (int off = 16; off; off >>= 1) s += __shfl_down_sync(0xffffffffu, s, off);
    if (lane == 0) out[(size_t)b * L_ + tt] = s + bfc[0];
}

__global__ __launch_bounds__(256) void k_copy(float* __restrict__ out) {
    int i = blockIdx.x * 256 + threadIdx.x;
    const int n = B_ * H_;
    if (i < n) {
        out[B_ * L_ + i] = g_H1fin[i];
        out[B_ * L_ + n + i] = g_H2[(size_t)(L_ - 1) * n + i];
    }
}

// ---------------------------------------------------------------------------
extern "C" void kernel_launch(void* const* d_in, const int* in_sizes, int n_in,
                              void* d_out, int out_size) {
    const float* x    = (const float*)d_in[0];
    const float* h1i  = (const float*)d_in[1];
    const float* h2i  = (const float*)d_in[2];
    const float* Wih1 = (const float*)d_in[3];
    const float* Whh1 = (const float*)d_in[4];
    const float* bih1 = (const float*)d_in[5];
    const float* bhh1 = (const float*)d_in[6];
    const float* Wih2 = (const float*)d_in[7];
    const float* Whh2 = (const float*)d_in[8];
    const float* bih2 = (const float*)d_in[9];
    const float* bhh2 = (const float*)d_in[10];
    const float* Wfc  = (const float*)d_in[11];
    const float* bfc  = (const float*)d_in[12];
    float* out = (float*)d_out;

    cudaFuncSetAttribute(k_steps, cudaFuncAttributeMaxDynamicSharedMemorySize, SMTOT_);

    void* bar_addr = nullptr;
    cudaGetSymbolAddress(&bar_addr, g_bars);
    cudaMemsetAsync(bar_addr, 0, 512 * sizeof(unsigned));

    k_prep_w<<<(G3_ * H_ + 255) / 256, 256>>>(Wih1, Whh1, Wih2, Whh2);
    k_prep_h<<<(B_ * H_ + 255) / 256, 256>>>(h1i, h2i);
    k_prep_x<<<(L_ * B_ * H_ + 255) / 256, 256>>>(x);

    k_steps<<<128, 512, SMTOT_>>>(h1i, h2i, bih1, bhh1, bih2, bhh2);

    k_fc<<<4096, 256>>>(Wfc, bfc, out);
    k_copy<<<(B_ * H_ + 255) / 256, 256>>>(out);
}